// round 17
// baseline (speedup 1.0000x reference)
#include <cuda_runtime.h>
#include <cuda_bf16.h>
#include <cuda_fp16.h>
#include <cstdint>

#define D256 256
#define NMAX 100000
#define EMAX 1600000
#define SCAN_BLK 1024

// ---------------- scratch (device globals) ----------------
__device__ __half g_xf16[(size_t)NMAX * D256];   // x plane
__device__ __half g_hf16[(size_t)NMAX * D256];   // h plane
__device__ __half g_mf16[(size_t)NMAX * D256];   // mean plane
__device__ __half g_cr16[(size_t)NMAX * D256];   // r-part partial (A@Wr)
__device__ int   g_cnt[NMAX + 1];
__device__ int   g_incl[NMAX + 1];
__device__ int   g_rowptr[NMAX + 2];
__device__ int   g_wptr[NMAX + 1];
__device__ int   g_col[EMAX];
__device__ int   g_part[256];
__device__ int   g_poff[256];
// pre-converted weights: [layer][n (256)][k (512)] fp16 (k<256: Wl, k>=256: Wr)
__device__ __half g_Whi[2 * 256 * 512];

// ---------------- helpers ----------------
__device__ __forceinline__ uint32_t pkh(float a, float b) {
    __half2 h = __floats2half2_rn(a, b);
    return *(uint32_t*)&h;
}
__device__ __forceinline__ uint32_t smem_u32(const void* p) {
    uint32_t a;
    asm("{ .reg .u64 t; cvta.to.shared.u64 t, %1; cvt.u32.u64 %0, t; }"
        : "=r"(a) : "l"(p));
    return a;
}
__device__ __forceinline__ void mma_f16(float* c, const uint32_t* a, const uint32_t* b) {
    asm volatile(
        "mma.sync.aligned.m16n8k16.row.col.f32.f16.f16.f32 "
        "{%0,%1,%2,%3}, {%4,%5,%6,%7}, {%8,%9}, {%0,%1,%2,%3};"
        : "+f"(c[0]), "+f"(c[1]), "+f"(c[2]), "+f"(c[3])
        : "r"(a[0]), "r"(a[1]), "r"(a[2]), "r"(a[3]), "r"(b[0]), "r"(b[1]));
}
__device__ __forceinline__ void ldsm_x4(uint32_t* r, uint32_t addr) {
    asm volatile("ldmatrix.sync.aligned.m8n8.x4.shared.b16 {%0,%1,%2,%3}, [%4];"
                 : "=r"(r[0]), "=r"(r[1]), "=r"(r[2]), "=r"(r[3]) : "r"(addr));
}
#define CP_ASYNC16(dst, src) asm volatile( \
    "cp.async.cg.shared.global [%0], [%1], 16;" :: "r"(dst), "l"(src) : "memory")
#define CP_COMMIT() asm volatile("cp.async.commit_group;" ::: "memory")

__device__ __forceinline__ void acc_h2(float& e, float& o, uint32_t w) {
    float2 f = __half22float2(*(const __half2*)&w);
    e += f.x; o += f.y;
}

// ---------------- small utility kernels ----------------
__global__ void zero_cnt_kernel(int n) {
    int i = blockIdx.x * blockDim.x + threadIdx.x;
    if (i < n) g_cnt[i] = 0;
}
__global__ void gather_x_kernel(const float* __restrict__ emb,
                                const int* __restrict__ idx, int N) {
    int t = blockIdx.x * blockDim.x + threadIdx.x;
    if (t >= N * 32) return;
    int r = t >> 5, c = t & 31;
    const float4* p = (const float4*)emb + (size_t)idx[r] * 64 + c * 2;
    float4 v0 = p[0], v1 = p[1];
    ((uint4*)g_xf16)[(size_t)r * 32 + c] =
        make_uint4(pkh(v0.x, v0.y), pkh(v0.z, v0.w), pkh(v1.x, v1.y), pkh(v1.z, v1.w));
}
__global__ void hist_kernel(const int* __restrict__ dst, int E) {
    int i = blockIdx.x * blockDim.x + threadIdx.x;
    if (i < E) atomicAdd(&g_cnt[dst[i]], 1);
}
__global__ void scan_local_kernel(int N) {
    __shared__ int s[SCAN_BLK];
    int i = blockIdx.x * SCAN_BLK + threadIdx.x;
    int v = (i < N) ? g_cnt[i] : 0;
    s[threadIdx.x] = v;
    __syncthreads();
    for (int off = 1; off < SCAN_BLK; off <<= 1) {
        int t = (threadIdx.x >= off) ? s[threadIdx.x - off] : 0;
        __syncthreads();
        s[threadIdx.x] += t;
        __syncthreads();
    }
    if (i < N) g_incl[i] = s[threadIdx.x];
    if (threadIdx.x == SCAN_BLK - 1) g_part[blockIdx.x] = s[SCAN_BLK - 1];
}
__global__ void scan_part_kernel(int nb) {
    __shared__ int s[128];
    int t = threadIdx.x;
    int v = (t < nb) ? g_part[t] : 0;
    s[t] = v;
    __syncthreads();
    for (int off = 1; off < 128; off <<= 1) {
        int u = (t >= off) ? s[t - off] : 0;
        __syncthreads();
        s[t] += u;
        __syncthreads();
    }
    if (t < nb) g_poff[t] = s[t] - v;   // exclusive
}
__global__ void scan_final_kernel(int N) {
    int i = blockIdx.x * SCAN_BLK + threadIdx.x;
    if (i < N) {
        int v = g_incl[i] + g_poff[blockIdx.x];
        g_rowptr[i + 1] = v;
        g_wptr[i] = v - g_cnt[i];
    }
    if (i == 0) g_rowptr[0] = 0;
}
__global__ void scatter_kernel(const int* __restrict__ src,
                               const int* __restrict__ dst, int E) {
    int i = blockIdx.x * blockDim.x + threadIdx.x;
    if (i < E) {
        int pos = atomicAdd(&g_wptr[dst[i]], 1);
        g_col[pos] = src[i];
    }
}
// mean aggregation: gathers fp16 plane, fp32 accumulate, writes fp16 mean plane
__global__ void aggregate_kernel(const __half* __restrict__ xf, int N) {
    int warp = (blockIdx.x * blockDim.x + threadIdx.x) >> 5;
    int lane = threadIdx.x & 31;
    if (warp >= N) return;
    int beg = g_rowptr[warp], end = g_rowptr[warp + 1];
    float4 a0 = make_float4(0.f, 0.f, 0.f, 0.f);
    float4 a1 = make_float4(0.f, 0.f, 0.f, 0.f);
    int j = beg;
    for (; j + 1 < end; j += 2) {
        const uint2* r0 = (const uint2*)(xf + (size_t)g_col[j] * D256);
        const uint2* r1 = (const uint2*)(xf + (size_t)g_col[j + 1] * D256);
        uint2 va0 = r0[lane], vb0 = r0[lane + 32];
        uint2 va1 = r1[lane], vb1 = r1[lane + 32];
        acc_h2(a0.x, a0.y, va0.x); acc_h2(a0.z, a0.w, va0.y);
        acc_h2(a1.x, a1.y, vb0.x); acc_h2(a1.z, a1.w, vb0.y);
        acc_h2(a0.x, a0.y, va1.x); acc_h2(a0.z, a0.w, va1.y);
        acc_h2(a1.x, a1.y, vb1.x); acc_h2(a1.z, a1.w, vb1.y);
    }
    if (j < end) {
        const uint2* r0 = (const uint2*)(xf + (size_t)g_col[j] * D256);
        uint2 va = r0[lane], vb = r0[lane + 32];
        acc_h2(a0.x, a0.y, va.x); acc_h2(a0.z, a0.w, va.y);
        acc_h2(a1.x, a1.y, vb.x); acc_h2(a1.z, a1.w, vb.y);
    }
    int deg = end - beg;
    float sc = 1.0f / (float)(deg > 1 ? deg : 1);
    uint2* mf = (uint2*)g_mf16 + (size_t)warp * 64;
    mf[lane]      = make_uint2(pkh(a0.x * sc, a0.y * sc), pkh(a0.z * sc, a0.w * sc));
    mf[lane + 32] = make_uint2(pkh(a1.x * sc, a1.y * sc), pkh(a1.z * sc, a1.w * sc));
}
__global__ void convW_kernel(const float* __restrict__ W1l, const float* __restrict__ W1r,
                             const float* __restrict__ W2l, const float* __restrict__ W2r) {
    int t = blockIdx.x * blockDim.x + threadIdx.x;
    if (t >= 2 * 256 * 512) return;
    int layer = t >> 17;
    int rem = t & 131071;
    int n = rem >> 9;
    int k = rem & 511;
    const float* Wl = layer ? W2l : W1l;
    const float* Wr = layer ? W2r : W1r;
    float v = (k < 256) ? Wl[k * 256 + n] : Wr[(k - 256) * 256 + n];
    g_Whi[t] = __float2half_rn(v);
}

// ---------------- persistent pipelined fp16 half-GEMM (K=256) ----------------
// C[M,256] = A@W(koff..koff+256) [+ bias] [+ Cprev]; outputs Cf (fp32) and/or Ch (fp16).
// CTA 256 thr, tile 128x128; warp tile 32x64. 8 K-chunks of 32, persistent grid,
// 2-stage cp.async pipeline across tile boundaries.
#define ROWB 80
#define STAGEB 20480
#define SM_GEMM (2 * STAGEB)

__global__ void __launch_bounds__(256, 2)
gemm_half_kernel(const __half* __restrict__ A, const __half* __restrict__ W, int koff,
                 const float* __restrict__ bias, const __half* __restrict__ Cprev,
                 float* __restrict__ Cf, __half* __restrict__ Ch, int M, int ntiles) {
    extern __shared__ char smem[];
    uint32_t sb = smem_u32(smem);
    int tid = threadIdx.x;
    int wid = tid >> 5, lane = tid & 31;
    int wm = wid >> 1, wn = wid & 1;
    int qr = lane >> 2, qc = (lane & 3) * 2;
    int lr = lane & 7, lg = lane >> 3;

    int stride = gridDim.x;
    int count = (ntiles - (int)blockIdx.x + stride - 1) / stride;
    if (count <= 0) return;
    int total_i = count * 8;

    float acc[2][8][4];
#pragma unroll
    for (int i = 0; i < 2; i++)
#pragma unroll
        for (int j = 0; j < 8; j++)
#pragma unroll
            for (int v = 0; v < 4; v++) acc[i][j][v] = 0.f;

    auto issue_i = [&](int gi, int stage) {
        int t = (int)blockIdx.x + (gi >> 3) * stride;
        int c = gi & 7;
        int bm = (t >> 1) * 128;
        int bn = (t & 1) * 128;
        int kl = c * 32;
        int k0 = koff + c * 32;
        uint32_t sbase = sb + stage * STAGEB;
#pragma unroll
        for (int it = 0; it < 4; it++) {
            int item = it * 256 + tid;          // 0..1023
            uint32_t dst;
            const __half* src;
            if (item < 512) {                   // A
                int r = item >> 2, kg = item & 3;
                int ar = bm + r; if (ar >= M) ar = M - 1;
                dst = sbase + r * ROWB + kg * 16;
                src = A + (size_t)ar * 256 + kl + kg * 8;
            } else {                            // W
                int itb = item - 512;
                int n = itb >> 2, kg = itb & 3;
                dst = sbase + 10240 + n * ROWB + kg * 16;
                src = W + (size_t)(bn + n) * 512 + k0 + kg * 8;
            }
            CP_ASYNC16(dst, src);
        }
        CP_COMMIT();
    };

    issue_i(0, 0);
    for (int gi = 0; gi < total_i; gi++) {
        int st = gi & 1;
        if (gi + 1 < total_i) {
            issue_i(gi + 1, st ^ 1);
            asm volatile("cp.async.wait_group 1;" ::: "memory");
        } else {
            asm volatile("cp.async.wait_group 0;" ::: "memory");
        }
        __syncthreads();

        uint32_t Ab  = sb + st * STAGEB;
        uint32_t Bhb = Ab + 10240;
        int arow0 = wm * 32 + lr + ((lg & 1) << 3);
        int brow0 = wn * 64 + lr + ((lg >> 1) << 3);
#pragma unroll
        for (int k16 = 0; k16 < 32; k16 += 16) {
            uint32_t akofs = (uint32_t)((k16 + ((lg >> 1) << 3)) * 2);
            uint32_t bkofs = (uint32_t)((k16 + ((lg & 1) << 3)) * 2);
            uint32_t ah[2][4];
            ldsm_x4(ah[0], Ab + arow0 * ROWB + akofs);
            ldsm_x4(ah[1], Ab + (arow0 + 16) * ROWB + akofs);
#pragma unroll
            for (int p = 0; p < 4; p++) {
                uint32_t bh[4];
                ldsm_x4(bh, Bhb + (brow0 + p * 16) * ROWB + bkofs);
#pragma unroll
                for (int mt = 0; mt < 2; mt++)
#pragma unroll
                    for (int j = 0; j < 2; j++)
                        mma_f16(acc[mt][p * 2 + j], ah[mt], &bh[2 * j]);
            }
        }
        __syncthreads();

        if ((gi & 7) == 7) {
            int t = (int)blockIdx.x + (gi >> 3) * stride;
            int bm = (t >> 1) * 128;
            int bn = (t & 1) * 128;
#pragma unroll
            for (int mt = 0; mt < 2; mt++) {
                int r0 = bm + wm * 32 + mt * 16 + qr;
#pragma unroll
                for (int nt = 0; nt < 8; nt++) {
                    int col = bn + wn * 64 + nt * 8 + qc;
                    float v00 = acc[mt][nt][0], v01 = acc[mt][nt][1];
                    float v10 = acc[mt][nt][2], v11 = acc[mt][nt][3];
                    if (bias) {
                        float2 bv = __ldg((const float2*)&bias[col]);
                        v00 += bv.x; v01 += bv.y; v10 += bv.x; v11 += bv.y;
                    }
                    if (Cprev) {
                        if (r0 < M) {
                            uint32_t cw = ((const uint32_t*)Cprev)[((size_t)r0 * 256 + col) >> 1];
                            float2 c2 = __half22float2(*(const __half2*)&cw);
                            v00 += c2.x; v01 += c2.y;
                        }
                        if (r0 + 8 < M) {
                            uint32_t cw = ((const uint32_t*)Cprev)[((size_t)(r0 + 8) * 256 + col) >> 1];
                            float2 c2 = __half22float2(*(const __half2*)&cw);
                            v10 += c2.x; v11 += c2.y;
                        }
                    }
                    if (Cf) {
                        if (r0 < M)
                            *(float2*)&Cf[(size_t)r0 * 256 + col] = make_float2(v00, v01);
                        if (r0 + 8 < M)
                            *(float2*)&Cf[(size_t)(r0 + 8) * 256 + col] = make_float2(v10, v11);
                    }
                    if (Ch) {
                        if (r0 < M)
                            ((uint32_t*)Ch)[((size_t)r0 * 256 + col) >> 1] = pkh(v00, v01);
                        if (r0 + 8 < M)
                            ((uint32_t*)Ch)[((size_t)(r0 + 8) * 256 + col) >> 1] = pkh(v10, v11);
                    }
                }
            }
#pragma unroll
            for (int i = 0; i < 2; i++)
#pragma unroll
                for (int j = 0; j < 8; j++)
#pragma unroll
                    for (int v = 0; v < 4; v++) acc[i][j][v] = 0.f;
        }
    }
}

__global__ void gather_out_kernel(const float* __restrict__ xf,
                                  const int* __restrict__ idxA, int nA,
                                  const int* __restrict__ idxB,
                                  float* __restrict__ out) {
    int r = blockIdx.x;
    int srow = (r < nA) ? idxA[r] : idxB[r - nA];
    ((float4*)(out + (size_t)r * D256))[threadIdx.x] =
        ((const float4*)(xf + (size_t)srow * D256))[threadIdx.x];
}

extern "C" void kernel_launch(void* const* d_in, const int* in_sizes, int n_in,
                              void* d_out, int out_size) {
    const float* emb = (const float*)d_in[0];
    const float* W1l = (const float*)d_in[1];
    const float* b1l = (const float*)d_in[2];
    const float* W1r = (const float*)d_in[3];
    const float* W2l = (const float*)d_in[4];
    const float* b2l = (const float*)d_in[5];
    const float* W2r = (const float*)d_in[6];
    const int* x_idx = (const int*)d_in[7];
    const int* edge  = (const int*)d_in[8];
    const int* drug  = (const int*)d_in[9];
    const int* se    = (const int*)d_in[10];

    int N = in_sizes[7];
    int E = in_sizes[8] / 2;
    const int* src = edge;
    const int* dst = edge + E;
    int nd = in_sizes[9];
    int ns = in_sizes[10];

    float* out   = (float*)d_out;
    float* out_x = out + (size_t)(nd + ns) * D256;

    __half *pxf, *phf, *pmf, *pcr, *pwh;
    cudaGetSymbolAddress((void**)&pxf, g_xf16);
    cudaGetSymbolAddress((void**)&phf, g_hf16);
    cudaGetSymbolAddress((void**)&pmf, g_mf16);
    cudaGetSymbolAddress((void**)&pcr, g_cr16);
    cudaGetSymbolAddress((void**)&pwh, g_Whi);

    static int nsm = 0;
    static cudaStream_t s1;
    static cudaEvent_t evStart, evX, evR1, evH, evR2;
    if (!nsm) {
        cudaDeviceGetAttribute(&nsm, cudaDevAttrMultiProcessorCount, 0);
        if (nsm <= 0) nsm = 148;
        cudaFuncSetAttribute(gemm_half_kernel,
                             cudaFuncAttributeMaxDynamicSharedMemorySize, SM_GEMM);
        cudaStreamCreateWithFlags(&s1, cudaStreamNonBlocking);
        cudaEventCreateWithFlags(&evStart, cudaEventDisableTiming);
        cudaEventCreateWithFlags(&evX, cudaEventDisableTiming);
        cudaEventCreateWithFlags(&evR1, cudaEventDisableTiming);
        cudaEventCreateWithFlags(&evH, cudaEventDisableTiming);
        cudaEventCreateWithFlags(&evR2, cudaEventDisableTiming);
    }

    int nb = (N + SCAN_BLK - 1) / SCAN_BLK;
    int ntiles = 2 * ((N + 127) / 128);
    int pgrid = 2 * nsm;
    if (pgrid > ntiles) pgrid = ntiles;

    // ---- fork s1 from the origin stream ----
    cudaEventRecord(evStart, 0);
    cudaStreamWaitEvent(s1, evStart, 0);

    // s1: x gather -> weight conv -> rgemm1 (x@W1r -> Cr)
    gather_x_kernel<<<(N * 32 + 255) / 256, 256, 0, s1>>>(emb, x_idx, N);
    cudaEventRecord(evX, s1);
    convW_kernel<<<(2 * 256 * 512 + 255) / 256, 256, 0, s1>>>(W1l, W1r, W2l, W2r);
    gemm_half_kernel<<<pgrid, 256, SM_GEMM, s1>>>(
        pxf, pwh, 256, nullptr, nullptr, nullptr, pcr, N, ntiles);
    cudaEventRecord(evR1, s1);

    // main: CSR build (concurrent with s1)
    zero_cnt_kernel<<<(N + 255) / 256, 256>>>(N);
    hist_kernel<<<(E + 255) / 256, 256>>>(dst, E);
    scan_local_kernel<<<nb, SCAN_BLK>>>(N);
    scan_part_kernel<<<1, 128>>>(nb);
    scan_final_kernel<<<nb, SCAN_BLK>>>(N);
    scatter_kernel<<<(E + 255) / 256, 256>>>(src, dst, E);

    // main: agg1 (needs CSR + x plane)
    cudaStreamWaitEvent(0, evX, 0);
    aggregate_kernel<<<(N * 32 + 255) / 256, 256>>>(pxf, N);

    // main: lgemm1 = mean@W1l + b1 + Cr -> h (needs agg1 + rgemm1)
    cudaStreamWaitEvent(0, evR1, 0);
    gemm_half_kernel<<<pgrid, 256, SM_GEMM>>>(
        pmf, pwh, 0, b1l, pcr, nullptr, phf, N, ntiles);
    cudaEventRecord(evH, 0);

    // s1: rgemm2 (h@W2r -> Cr), concurrent with agg2
    cudaStreamWaitEvent(s1, evH, 0);
    gemm_half_kernel<<<pgrid, 256, SM_GEMM, s1>>>(
        phf, pwh + 256 * 512, 256, nullptr, nullptr, nullptr, pcr, N, ntiles);
    cudaEventRecord(evR2, s1);

    // main: agg2
    aggregate_kernel<<<(N * 32 + 255) / 256, 256>>>(phf, N);

    // main: lgemm2 = mean@W2l + b2 + Cr -> out_x (fp32)
    cudaStreamWaitEvent(0, evR2, 0);
    gemm_half_kernel<<<pgrid, 256, SM_GEMM>>>(
        pmf, pwh + 256 * 512, 0, b2l, pcr, out_x, nullptr, N, ntiles);

    // main: output gathers
    gather_out_kernel<<<nd + ns, 64>>>(out_x, drug, nd, se, out);
}